// round 1
// baseline (speedup 1.0000x reference)
#include <cuda_runtime.h>
#include <cuda_bf16.h>
#include <cstdint>

// Problem constants (fixed by reference setup_inputs)
#define B_   16
#define D_   256
#define H_   32
#define W_   32
#define S_   1024            // H*W
#define NTOK 16384           // B*S
#define KC   8192            // codebook size
#define BDS  4194304         // B*D*S

// Tiling for the argmin (distance) kernel
#define TM   128             // tokens per block
#define TK   128             // codes per k-tile
#define DC   64              // d-chunk streamed through smem

#define XS_ELEMS (D_ * TM)       // 32768 floats = 128 KB
#define ES_ELEMS (DC * TK)       // 8192 floats  = 32 KB
#define CS_ELEMS (TK)            // 128 floats
#define SMEM_BYTES ((XS_ELEMS + ES_ELEMS + CS_ELEMS) * sizeof(float))

// Device scratch (no allocations allowed)
__device__ float g_csq[KC];
__device__ int   g_ind[NTOK];

// ---------------------------------------------------------------------------
// Kernel A: c[k] = ||e_k||^2  (E is [D, K] row-major, column k strided by K)
// ---------------------------------------------------------------------------
__global__ void vq_csq_kernel(const float* __restrict__ E) {
    int k = blockIdx.x * blockDim.x + threadIdx.x;
    if (k >= KC) return;
    float a = 0.f;
#pragma unroll 8
    for (int d = 0; d < D_; ++d) {
        float v = E[(size_t)d * KC + k];
        a = fmaf(v, v, a);
    }
    g_csq[k] = a;
}

// ---------------------------------------------------------------------------
// Kernel B: per-token argmin_k ( c_k - 2 * x·e_k )
//   Block: 256 threads = 16 (token groups) x 16 (code groups)
//   Each thread: 8x8 microtile of (tokens x codes)
//   x tile [D=256][TM=128] resident in smem for the whole kernel.
// ---------------------------------------------------------------------------
__global__ __launch_bounds__(256, 1)
void vq_argmin_kernel(const float* __restrict__ x, const float* __restrict__ E) {
    extern __shared__ float smem[];
    float* xs = smem;                     // [D_][TM]
    float* es = smem + XS_ELEMS;          // [DC][TK]
    float* cs = smem + XS_ELEMS + ES_ELEMS; // [TK]

    const int tid = threadIdx.x;
    const int ty  = tid >> 4;             // 0..15 token group
    const int tx  = tid & 15;             // 0..15 code group
    const int row0 = ty * 8;
    const int col0 = tx * 8;

    const int n0 = blockIdx.x * TM;       // first token of this block (TM divides S_)
    const int b  = n0 / S_;
    const int s0 = n0 % S_;
    const size_t xbase = ((size_t)b * D_) * S_ + s0;

    // Load resident x tile: xs[d][t] = x[b, d, s0+t]
    for (int idx = tid; idx < XS_ELEMS; idx += 256) {
        int d = idx >> 7;                 // /TM
        int t = idx & (TM - 1);
        xs[idx] = x[xbase + (size_t)d * S_ + t];
    }

    float best[8];
    int   bidx[8];
#pragma unroll
    for (int i = 0; i < 8; ++i) { best[i] = 3.402823466e+38f; bidx[i] = 0; }

    for (int k0 = 0; k0 < KC; k0 += TK) {
        float acc[8][8];
#pragma unroll
        for (int i = 0; i < 8; ++i)
#pragma unroll
            for (int j = 0; j < 8; ++j) acc[i][j] = 0.f;

        for (int dc = 0; dc < D_; dc += DC) {
            __syncthreads();
            // Stream E chunk: es[dd][j] = E[(dc+dd)*K + k0 + j]
            for (int idx = tid; idx < ES_ELEMS; idx += 256) {
                int dd = idx >> 7;        // /TK
                int j  = idx & (TK - 1);
                es[idx] = E[(size_t)(dc + dd) * KC + k0 + j];
            }
            if (dc == 0) {
                for (int j = tid; j < TK; j += 256) cs[j] = g_csq[k0 + j];
            }
            __syncthreads();

#pragma unroll 4
            for (int dd = 0; dd < DC; ++dd) {
                const float* xrow = xs + (size_t)(dc + dd) * TM + row0;
                const float* erow = es + (size_t)dd * TK + col0;
                float xr[8], er[8];
                float4 t0 = *(const float4*)(xrow);
                float4 t1 = *(const float4*)(xrow + 4);
                xr[0]=t0.x; xr[1]=t0.y; xr[2]=t0.z; xr[3]=t0.w;
                xr[4]=t1.x; xr[5]=t1.y; xr[6]=t1.z; xr[7]=t1.w;
                float4 u0 = *(const float4*)(erow);
                float4 u1 = *(const float4*)(erow + 4);
                er[0]=u0.x; er[1]=u0.y; er[2]=u0.z; er[3]=u0.w;
                er[4]=u1.x; er[5]=u1.y; er[6]=u1.z; er[7]=u1.w;
#pragma unroll
                for (int i = 0; i < 8; ++i)
#pragma unroll
                    for (int j = 0; j < 8; ++j)
                        acc[i][j] = fmaf(xr[i], er[j], acc[i][j]);
            }
        }

        // Epilogue: partial distance m = c_k - 2*dot; track per-token running min.
        float cv[8];
#pragma unroll
        for (int j = 0; j < 8; ++j) cv[j] = cs[col0 + j];
#pragma unroll
        for (int i = 0; i < 8; ++i) {
#pragma unroll
            for (int j = 0; j < 8; ++j) {
                float m = fmaf(-2.f, acc[i][j], cv[j]);
                if (m < best[i]) { best[i] = m; bidx[i] = k0 + col0 + j; }
            }
        }
    }

    // Reduce across the 16 code-group lanes (contiguous 16-lane segments).
    // Prefer lower index on exact ties (matches jnp.argmin first-occurrence).
#pragma unroll
    for (int i = 0; i < 8; ++i) {
        float bv = best[i];
        int   bi = bidx[i];
        for (int off = 8; off >= 1; off >>= 1) {
            float ov = __shfl_xor_sync(0xffffffffu, bv, off, 16);
            int   oi = __shfl_xor_sync(0xffffffffu, bi, off, 16);
            if (ov < bv || (ov == bv && oi < bi)) { bv = ov; bi = oi; }
        }
        if (tx == 0) g_ind[n0 + row0 + i] = bi;
    }
}

// ---------------------------------------------------------------------------
// Kernel C: outputs.
//   out[0 : BDS)        = quantized_x_d = x + (q - x)   (exact fp32 op order)
//   out[BDS : 2*BDS)    = quantized_x   = q
//   out[2*BDS : +NTOK)  = ind (as float)
//   Thread (d, n): consecutive threads vary n -> coalesced x/out access.
// ---------------------------------------------------------------------------
__global__ void vq_gather_kernel(const float* __restrict__ x,
                                 const float* __restrict__ E,
                                 float* __restrict__ out) {
    size_t tid = (size_t)blockIdx.x * blockDim.x + threadIdx.x;  // D_*NTOK total
    int n = (int)(tid & (NTOK - 1));
    int d = (int)(tid >> 14);            // /NTOK
    int idx = g_ind[n];
    int b = n >> 10;                     // /S_
    int s = n & (S_ - 1);
    float q  = E[(size_t)d * KC + idx];
    size_t xo = ((size_t)b * D_ + d) * S_ + s;
    float xv = x[xo];
    out[xo]        = xv + (q - xv);      // straight-through: replicate rounding
    out[BDS + xo]  = q;
    if (d == 0) out[2 * (size_t)BDS + n] = (float)idx;
}

// ---------------------------------------------------------------------------
extern "C" void kernel_launch(void* const* d_in, const int* in_sizes, int n_in,
                              void* d_out, int out_size) {
    const float* x = (const float*)d_in[0];   // [B, D, H, W] fp32
    const float* E = (const float*)d_in[1];   // [D, K] fp32
    float* out = (float*)d_out;

    cudaFuncSetAttribute(vq_argmin_kernel,
                         cudaFuncAttributeMaxDynamicSharedMemorySize,
                         (int)SMEM_BYTES);

    vq_csq_kernel<<<KC / 256, 256>>>(E);
    vq_argmin_kernel<<<NTOK / TM, 256, SMEM_BYTES>>>(x, E);
    vq_gather_kernel<<<(D_ * NTOK) / 256, 256>>>(x, E, out);
}